// round 4
// baseline (speedup 1.0000x reference)
#include <cuda_runtime.h>
#include <math_constants.h>

// Problem constants (from reference setup_inputs)
constexpr int B  = 4;
constexpr int H  = 64;
constexpr int W  = 64;
constexpr int C  = 256;
constexpr int NR = 256;   // rois per image
constexpr int PH = 7;
constexpr int PW = 7;

constexpr int C4   = C / 4;        // float4 groups per position = 64
constexpr int NTHR = PW * 32;      // 224: one warp per pw bin, 32 lanes x 32B

// Reproduce the reference's _axis_bins window math exactly.
__device__ __forceinline__ void axis_bins(float center, float size, int pooled,
                                          int limit, int& start_o, int& len_o,
                                          int& step_o) {
    int s = (int)(center - size * 0.5f);   // trunc-toward-zero == astype(int32)
    if (s < 0) s = 0;
    int e = (int)(center + size * 0.5f);
    if (e > limit) e = limit;

    int pad_raw = pooled - (e - s);
    if (pad_raw > 0) {
        int pad    = (pad_raw + 1) >> 1;   // ceil(pad_raw/2), pad_raw>0
        int top    = limit - e;
        int bottom = s;
        int ns, ne;
        if (top < pad)          { ns = s - (2 * pad - top);  ne = e + top; }
        else if (bottom < pad)  { ns = s - bottom;           ne = e + (2 * pad - bottom); }
        else                    { ns = s - pad;              ne = e + pad; }
        s = ns; e = ne;
    }
    int length = e - s;
    int step   = length / pooled;
    if (step < 1) step = 1;
    start_o = s; len_o = length; step_o = step;
}

__global__ __launch_bounds__(NTHR, 7)
void roi_pool_kernel(const float4* __restrict__ fm,     // [B,H,W,C/4]
                     const float*  __restrict__ rois,   // [B,NR,4] (x,y,w,h)
                     float4*       __restrict__ out)    // [B,NR,PH,PW,C/4]
{
    const int bn = blockIdx.x;          // b*NR + n
    const int b  = bn >> 8;             // NR == 256
    const int ph = blockIdx.y;          // row-bin handled by this block

    const float x = rois[bn * 4 + 0];
    const float y = rois[bn * 4 + 1];
    const float w = rois[bn * 4 + 2];
    const float h = rois[bn * 4 + 3];

    int rs, rlen, rstep;  axis_bins(y, h, PH, H, rs, rlen, rstep);
    int cs, clen, cstep;  axis_bins(x, w, PW, W, cs, clen, cstep);

    // Row band for this block's ph bin, clamped to the map.
    int r0 = rs + ph * rstep;
    int r1 = (ph == PH - 1) ? (rs + rlen) : (r0 + rstep);
    if (r0 < 0) r0 = 0;
    if (r1 > H) r1 = H;

    const int lane = threadIdx.x & 31;   // channel chunk: 2 float4 = 32B
    const int pw   = threadIdx.x >> 5;   // warp id == pw bin (0..6)

    // Column range for this warp's pw bin, clamped to the map.
    int c0 = cs + pw * cstep;
    int c1 = (pw == PW - 1) ? (cs + clen) : (c0 + cstep);
    if (c0 < 0) c0 = 0;
    if (c1 > W) c1 = W;

    const float4* fmb = fm + (size_t)b * (H * W * C4) + lane * 2;

    float4 m0, m1;
    m0.x = m0.y = m0.z = m0.w = -CUDART_INF_F;
    m1 = m0;

    for (int r = r0; r < r1; ++r) {
        const float4* p = fmb + (r * W + c0) * C4;
        for (int cc = c0; cc < c1; ++cc, p += C4) {
            float4 v0 = __ldg(p);
            float4 v1 = __ldg(p + 1);
            m0.x = fmaxf(m0.x, v0.x);  m0.y = fmaxf(m0.y, v0.y);
            m0.z = fmaxf(m0.z, v0.z);  m0.w = fmaxf(m0.w, v0.w);
            m1.x = fmaxf(m1.x, v1.x);  m1.y = fmaxf(m1.y, v1.y);
            m1.z = fmaxf(m1.z, v1.z);  m1.w = fmaxf(m1.w, v1.w);
        }
    }

    float4* o = out + (((size_t)bn * PH + ph) * PW + pw) * C4 + lane * 2;
    o[0] = m0;
    o[1] = m1;
}

extern "C" void kernel_launch(void* const* d_in, const int* in_sizes, int n_in,
                              void* d_out, int out_size) {
    const float* fm   = (const float*)d_in[0];
    const float* rois = (const float*)d_in[1];
    if (n_in >= 2 && in_sizes[0] == B * NR * 4 && in_sizes[1] == B * H * W * C) {
        fm   = (const float*)d_in[1];
        rois = (const float*)d_in[0];
    }

    dim3 grid(B * NR, PH);
    roi_pool_kernel<<<grid, NTHR>>>((const float4*)fm, rois, (float4*)d_out);
}

// round 6
// speedup vs baseline: 1.2463x; 1.2463x over previous
#include <cuda_runtime.h>
#include <math_constants.h>

// Problem constants (from reference setup_inputs)
constexpr int B  = 4;
constexpr int H  = 64;
constexpr int W  = 64;
constexpr int C  = 256;
constexpr int NR = 256;   // rois per image
constexpr int PH = 7;
constexpr int PW = 7;

constexpr int C4   = C / 4;        // float4 groups per position = 64
constexpr int NTHR = PW * 32;      // 224: one warp per pw bin

// Reproduce the reference's _axis_bins window math exactly.
__device__ __forceinline__ void axis_bins(float center, float size, int pooled,
                                          int limit, int& start_o, int& len_o,
                                          int& step_o) {
    int s = (int)(center - size * 0.5f);   // trunc-toward-zero == astype(int32)
    if (s < 0) s = 0;
    int e = (int)(center + size * 0.5f);
    if (e > limit) e = limit;

    int pad_raw = pooled - (e - s);
    if (pad_raw > 0) {
        int pad    = (pad_raw + 1) >> 1;   // ceil(pad_raw/2), pad_raw>0
        int top    = limit - e;
        int bottom = s;
        int ns, ne;
        if (top < pad)          { ns = s - (2 * pad - top);  ne = e + top; }
        else if (bottom < pad)  { ns = s - bottom;           ne = e + (2 * pad - bottom); }
        else                    { ns = s - pad;              ne = e + pad; }
        s = ns; e = ne;
    }
    int length = e - s;
    int step   = length / pooled;
    if (step < 1) step = 1;
    start_o = s; len_o = length; step_o = step;
}

__global__ __launch_bounds__(NTHR, 7)
void roi_pool_kernel(const float4* __restrict__ fm,     // [B,H,W,C/4]
                     const float*  __restrict__ rois,   // [B,NR,4] (x,y,w,h)
                     float4*       __restrict__ out)    // [B,NR,PH,PW,C/4]
{
    const int bn = blockIdx.x;          // b*NR + n
    const int b  = bn >> 8;             // NR == 256
    const int ph = blockIdx.y;          // row-bin handled by this block

    const float x = rois[bn * 4 + 0];
    const float y = rois[bn * 4 + 1];
    const float w = rois[bn * 4 + 2];
    const float h = rois[bn * 4 + 3];

    int rs, rlen, rstep;  axis_bins(y, h, PH, H, rs, rlen, rstep);
    int cs, clen, cstep;  axis_bins(x, w, PW, W, cs, clen, cstep);

    // Row band for this block's ph bin, clamped to the map.
    int r0 = rs + ph * rstep;
    int r1 = (ph == PH - 1) ? (rs + rlen) : (r0 + rstep);
    if (r0 < 0) r0 = 0;
    if (r1 > H) r1 = H;

    const int lane = threadIdx.x & 31;
    const int pw   = threadIdx.x >> 5;   // warp id == pw bin (0..6)

    // Column range for this warp's pw bin, clamped to the map.
    int c0 = cs + pw * cstep;
    int c1 = (pw == PW - 1) ? (cs + clen) : (c0 + cstep);
    if (c0 < 0) c0 = 0;
    if (c1 > W) c1 = W;

    // Coalesced split: lane L owns float4 L (first 512B of the position)
    // and float4 L+32 (second 512B). Each LDG.128 is warp-dense.
    const float4* fmb = fm + (size_t)b * (H * W * C4) + lane;

    float4 m0, m1;
    m0.x = m0.y = m0.z = m0.w = -CUDART_INF_F;
    m1 = m0;

    for (int r = r0; r < r1; ++r) {
        const float4* p = fmb + (r * W + c0) * C4;
        for (int cc = c0; cc < c1; ++cc, p += C4) {
            float4 v0 = __ldg(p);
            float4 v1 = __ldg(p + 32);
            m0.x = fmaxf(m0.x, v0.x);  m0.y = fmaxf(m0.y, v0.y);
            m0.z = fmaxf(m0.z, v0.z);  m0.w = fmaxf(m0.w, v0.w);
            m1.x = fmaxf(m1.x, v1.x);  m1.y = fmaxf(m1.y, v1.y);
            m1.z = fmaxf(m1.z, v1.z);  m1.w = fmaxf(m1.w, v1.w);
        }
    }

    float4* o = out + (((size_t)bn * PH + ph) * PW + pw) * C4 + lane;
    o[0]  = m0;
    o[32] = m1;
}

extern "C" void kernel_launch(void* const* d_in, const int* in_sizes, int n_in,
                              void* d_out, int out_size) {
    const float* fm   = (const float*)d_in[0];
    const float* rois = (const float*)d_in[1];
    if (n_in >= 2 && in_sizes[0] == B * NR * 4 && in_sizes[1] == B * H * W * C) {
        fm   = (const float*)d_in[1];
        rois = (const float*)d_in[0];
    }

    dim3 grid(B * NR, PH);
    roi_pool_kernel<<<grid, NTHR>>>((const float4*)fm, rois, (float4*)d_out);
}

// round 7
// speedup vs baseline: 1.4410x; 1.1563x over previous
#include <cuda_runtime.h>
#include <math_constants.h>

// Problem constants (from reference setup_inputs)
constexpr int B  = 4;
constexpr int H  = 64;
constexpr int W  = 64;
constexpr int C  = 256;
constexpr int NR = 256;   // rois per image
constexpr int PH = 7;
constexpr int PW = 7;

constexpr int C4    = C / 4;       // float4 groups per position = 64
constexpr int NTHR  = PW * 32;     // 224: one warp per pw bin
constexpr int NROIS = B * NR;      // 1024

// Precomputed per-ROI bin geometry (clamped to the map).
__device__ int2 g_rows[NROIS * PH];   // {r0, r1} per (roi, ph)
__device__ int2 g_cols[NROIS * PW];   // {c0, c1} per (roi, pw)

// Reproduce the reference's _axis_bins window math exactly.
__device__ __forceinline__ void axis_bins(float center, float size, int pooled,
                                          int limit, int& start_o, int& len_o,
                                          int& step_o) {
    int s = (int)(center - size * 0.5f);   // trunc-toward-zero == astype(int32)
    if (s < 0) s = 0;
    int e = (int)(center + size * 0.5f);
    if (e > limit) e = limit;

    int pad_raw = pooled - (e - s);
    if (pad_raw > 0) {
        int pad    = (pad_raw + 1) >> 1;   // ceil(pad_raw/2), pad_raw>0
        int top    = limit - e;
        int bottom = s;
        int ns, ne;
        if (top < pad)          { ns = s - (2 * pad - top);  ne = e + top; }
        else if (bottom < pad)  { ns = s - bottom;           ne = e + (2 * pad - bottom); }
        else                    { ns = s - pad;              ne = e + pad; }
        s = ns; e = ne;
    }
    int length = e - s;
    int step   = length / pooled;
    if (step < 1) step = 1;
    start_o = s; len_o = length; step_o = step;
}

__global__ void geom_kernel(const float* __restrict__ rois) {
    int bn = blockIdx.x * blockDim.x + threadIdx.x;
    if (bn >= NROIS) return;

    const float x = rois[bn * 4 + 0];
    const float y = rois[bn * 4 + 1];
    const float w = rois[bn * 4 + 2];
    const float h = rois[bn * 4 + 3];

    int rs, rlen, rstep;  axis_bins(y, h, PH, H, rs, rlen, rstep);
    int cs, clen, cstep;  axis_bins(x, w, PW, W, cs, clen, cstep);

    #pragma unroll
    for (int ph = 0; ph < PH; ++ph) {
        int r0 = rs + ph * rstep;
        int r1 = (ph == PH - 1) ? (rs + rlen) : (r0 + rstep);
        if (r0 < 0) r0 = 0;
        if (r1 > H) r1 = H;
        g_rows[bn * PH + ph] = make_int2(r0, r1);
    }
    #pragma unroll
    for (int pw = 0; pw < PW; ++pw) {
        int c0 = cs + pw * cstep;
        int c1 = (pw == PW - 1) ? (cs + clen) : (c0 + cstep);
        if (c0 < 0) c0 = 0;
        if (c1 > W) c1 = W;
        g_cols[bn * PW + pw] = make_int2(c0, c1);
    }
}

__global__ __launch_bounds__(NTHR, 6)
void roi_pool_kernel(const float4* __restrict__ fm,     // [B,H,W,C/4]
                     float4*       __restrict__ out)    // [B,NR,PH,PW,C/4]
{
    const int bn = blockIdx.x;          // b*NR + n
    const int b  = bn >> 8;             // NR == 256
    const int ph = blockIdx.y;          // row-bin handled by this block

    const int lane = threadIdx.x & 31;
    const int pw   = threadIdx.x >> 5;  // warp id == pw bin (0..6)

    const int2 rr = g_rows[bn * PH + ph];
    const int2 cr = g_cols[bn * PW + pw];
    const int r0 = rr.x, r1 = rr.y;
    const int c0 = cr.x, c1 = cr.y;

    // Coalesced split: lane L owns float4 L (first 512B of each position)
    // and float4 L+32 (second 512B). Each LDG.128 is warp-dense.
    const float4* fmb = fm + (size_t)b * (H * W * C4) + lane;

    float4 m0, m1;
    m0.x = m0.y = m0.z = m0.w = -CUDART_INF_F;
    m1 = m0;

    for (int r = r0; r < r1; ++r) {
        const float4* p = fmb + (r * W + c0) * C4;
        int cc = c0;
        // Paired body: 4 independent LDG.128 in flight per iteration.
        for (; cc + 2 <= c1; cc += 2, p += 2 * C4) {
            float4 v0 = __ldg(p);
            float4 v1 = __ldg(p + 32);
            float4 v2 = __ldg(p + C4);
            float4 v3 = __ldg(p + C4 + 32);
            m0.x = fmaxf(m0.x, fmaxf(v0.x, v2.x));
            m0.y = fmaxf(m0.y, fmaxf(v0.y, v2.y));
            m0.z = fmaxf(m0.z, fmaxf(v0.z, v2.z));
            m0.w = fmaxf(m0.w, fmaxf(v0.w, v2.w));
            m1.x = fmaxf(m1.x, fmaxf(v1.x, v3.x));
            m1.y = fmaxf(m1.y, fmaxf(v1.y, v3.y));
            m1.z = fmaxf(m1.z, fmaxf(v1.z, v3.z));
            m1.w = fmaxf(m1.w, fmaxf(v1.w, v3.w));
        }
        if (cc < c1) {    // odd-width tail, no duplicate traffic
            float4 v0 = __ldg(p);
            float4 v1 = __ldg(p + 32);
            m0.x = fmaxf(m0.x, v0.x);  m0.y = fmaxf(m0.y, v0.y);
            m0.z = fmaxf(m0.z, v0.z);  m0.w = fmaxf(m0.w, v0.w);
            m1.x = fmaxf(m1.x, v1.x);  m1.y = fmaxf(m1.y, v1.y);
            m1.z = fmaxf(m1.z, v1.z);  m1.w = fmaxf(m1.w, v1.w);
        }
    }

    float4* o = out + (((size_t)bn * PH + ph) * PW + pw) * C4 + lane;
    o[0]  = m0;
    o[32] = m1;
}

extern "C" void kernel_launch(void* const* d_in, const int* in_sizes, int n_in,
                              void* d_out, int out_size) {
    const float* fm   = (const float*)d_in[0];
    const float* rois = (const float*)d_in[1];
    if (n_in >= 2 && in_sizes[0] == B * NR * 4 && in_sizes[1] == B * H * W * C) {
        fm   = (const float*)d_in[1];
        rois = (const float*)d_in[0];
    }

    geom_kernel<<<(NROIS + 255) / 256, 256>>>(rois);

    dim3 grid(B * NR, PH);
    roi_pool_kernel<<<grid, NTHR>>>((const float4*)fm, (float4*)d_out);
}